// round 2
// baseline (speedup 1.0000x reference)
#include <cuda_runtime.h>
#include <math_constants.h>

#define NROW 8192
#define DIN  1024
#define DD   256
#define KK   30
#define SCALE_F 0.0625f   // 256^-0.5

// ---------------- device scratch (no allocations allowed) ----------------
__device__ float g_A[NROW * DD];
__device__ float g_B[NROW * DD];
__device__ float g_eh[NROW * DD];
__device__ float g_et[NROW * DD];
__device__ float g_S[(size_t)NROW * NROW];     // 256 MB score matrix
__device__ float g_eNh[NROW * DD];
__device__ float g_tw[NROW * KK];
__device__ int   g_ti[NROW * KK];
__device__ float g_att[NROW];
__device__ float g_red2[2];
__device__ float g_part[64 * DD];

// ---------------- generic tiled SGEMM: C = act(scale*A@B(^T) + bias) (+C) --
// A: [M,Kc] row-major. TB=false: B [Kc,Nc] row-major. TB=true: B [Nc,Kc].
// BM=BN=64, BK=16, 256 threads, 4x4 per-thread microtile.
template <bool TB>
__global__ void gemm_kernel(const float* __restrict__ A, const float* __restrict__ B,
                            const float* __restrict__ bias, float* __restrict__ C,
                            int M, int Nc, int Kc, float scale, int act, int accum)
{
    __shared__ float As[16][64];
    __shared__ float Bs[16][64];
    const int tid = threadIdx.x;
    const int bm = blockIdx.y * 64, bn = blockIdx.x * 64;
    const int tx = tid & 15, ty = tid >> 4;

    float acc[4][4];
#pragma unroll
    for (int i = 0; i < 4; i++)
#pragma unroll
        for (int j = 0; j < 4; j++) acc[i][j] = 0.f;

    const int arow = tid >> 2;            // 0..63
    const int akc  = (tid & 3) << 2;      // 0,4,8,12
    const int brow = tid >> 4;            // 0..15
    const int bcol = (tid & 15) << 2;     // 0..60

    for (int k0 = 0; k0 < Kc; k0 += 16) {
        float4 va = *(const float4*)(A + (size_t)(bm + arow) * Kc + k0 + akc);
        As[akc + 0][arow] = va.x; As[akc + 1][arow] = va.y;
        As[akc + 2][arow] = va.z; As[akc + 3][arow] = va.w;
        if (TB) {
            float4 vb = *(const float4*)(B + (size_t)(bn + arow) * Kc + k0 + akc);
            Bs[akc + 0][arow] = vb.x; Bs[akc + 1][arow] = vb.y;
            Bs[akc + 2][arow] = vb.z; Bs[akc + 3][arow] = vb.w;
        } else {
            float4 vb = *(const float4*)(B + (size_t)(k0 + brow) * Nc + bn + bcol);
            *(float4*)&Bs[brow][bcol] = vb;
        }
        __syncthreads();
#pragma unroll
        for (int k = 0; k < 16; k++) {
            float4 a4 = *(const float4*)&As[k][ty << 2];
            float4 b4 = *(const float4*)&Bs[k][tx << 2];
            float ar[4] = {a4.x, a4.y, a4.z, a4.w};
            float br[4] = {b4.x, b4.y, b4.z, b4.w};
#pragma unroll
            for (int i = 0; i < 4; i++)
#pragma unroll
                for (int j = 0; j < 4; j++) acc[i][j] += ar[i] * br[j];
        }
        __syncthreads();
    }

#pragma unroll
    for (int i = 0; i < 4; i++) {
        const int m = bm + (ty << 2) + i;
#pragma unroll
        for (int j = 0; j < 4; j++) {
            const int n = bn + (tx << 2) + j;
            float v = acc[i][j] * scale;
            if (bias) v += bias[n];
            if (act == 1) v = fmaxf(v, 0.f);
            else if (act == 2) v = v > 0.f ? v : 0.01f * v;
            const size_t o = (size_t)m * Nc + n;
            if (accum) v += C[o];
            C[o] = v;
        }
    }
}

// ---------------- top-30 per row (one block / row, owner-rescan argmax) ----
__global__ void topk_kernel(const float* __restrict__ S,
                            float* __restrict__ tw, int* __restrict__ ti)
{
    __shared__ float s_row[NROW];
    __shared__ float s_wv[8];
    __shared__ int   s_wi[8];
    __shared__ float s_bv; __shared__ int s_bi;
    const int row = blockIdx.x, tid = threadIdx.x;
    const float* Sr = S + (size_t)row * NROW;
    for (int j = tid; j < NROW; j += 256) s_row[j] = Sr[j];
    __syncthreads();

    const int base = tid << 5;                // each thread owns 32 contiguous
    float lv = -CUDART_INF_F; int li = 0;
#pragma unroll
    for (int j = 0; j < 32; j++) { float v = s_row[base + j]; if (v > lv) { lv = v; li = base + j; } }

    const int lane = tid & 31, warp = tid >> 5;
    for (int s = 0; s < KK; s++) {
        float v = lv; int i = li;
#pragma unroll
        for (int off = 16; off; off >>= 1) {
            float v2 = __shfl_down_sync(0xffffffffu, v, off);
            int   i2 = __shfl_down_sync(0xffffffffu, i, off);
            if (v2 > v || (v2 == v && i2 < i)) { v = v2; i = i2; }
        }
        if (lane == 0) { s_wv[warp] = v; s_wi[warp] = i; }
        __syncthreads();
        if (tid < 8) {
            v = s_wv[tid]; i = s_wi[tid];
#pragma unroll
            for (int off = 4; off; off >>= 1) {
                float v2 = __shfl_down_sync(0xffu, v, off);
                int   i2 = __shfl_down_sync(0xffu, i, off);
                if (v2 > v || (v2 == v && i2 < i)) { v = v2; i = i2; }
            }
            if (tid == 0) {
                s_bv = v; s_bi = i;
                tw[(size_t)row * KK + s] = v;
                ti[(size_t)row * KK + s] = i;
            }
        }
        __syncthreads();
        const int sel = s_bi;
        if (sel >= base && sel < base + 32) {      // only owner rescans
            s_row[sel] = -CUDART_INF_F;
            lv = -CUDART_INF_F; li = 0;
#pragma unroll
            for (int j = 0; j < 32; j++) { float vv = s_row[base + j]; if (vv > lv) { lv = vv; li = base + j; } }
        }
        __syncthreads();
    }
}

// ---------------- gated message + second softmax + aggregation -------------
__global__ void message_kernel(const float* __restrict__ eh, const float* __restrict__ et,
                               const float* __restrict__ tw, const int* __restrict__ ti,
                               float* __restrict__ eNh)
{
    __shared__ float s_p[KK];
    __shared__ float s_ka[KK];
    __shared__ float s_r1[8], s_r2[8];
    const int row = blockIdx.x, d = threadIdx.x;   // 256 threads = D
    const int lane = d & 31, warp = d >> 5;

    if (d == 0) {   // softmax over top-k logits (sorted desc, [0] is max)
        float mx = tw[(size_t)row * KK];
        float pv[KK]; float z = 0.f;
#pragma unroll
        for (int k = 0; k < KK; k++) { pv[k] = expf(tw[(size_t)row * KK + k] - mx); z += pv[k]; }
        const float iz = 1.f / z;
#pragma unroll
        for (int k = 0; k < KK; k++) s_p[k] = pv[k] * iz;
    }
    __syncthreads();

    const float ehd = eh[(size_t)row * DD + d];
    float nb[KK];
#pragma unroll
    for (int k = 0; k < KK; k++) {
        const int j = ti[(size_t)row * KK + k];
        const float nbv = et[(size_t)j * DD + d];
        nb[k] = nbv;
        const float p = s_p[k];
        // gate = tanh(e_h + p*Nb + (1-p)*e_h) = tanh((2-p)*e_h + p*Nb)
        const float gate = tanhf((2.f - p) * ehd + p * nbv);
        float s1 = nbv, s2 = gate;
#pragma unroll
        for (int off = 16; off; off >>= 1) {
            s1 += __shfl_down_sync(0xffffffffu, s1, off);
            s2 += __shfl_down_sync(0xffffffffu, s2, off);
        }
        if (lane == 0) { s_r1[warp] = s1; s_r2[warp] = s2; }
        __syncthreads();
        if (d == 0) {
            float a = 0.f, b = 0.f;
            for (int w = 0; w < 8; w++) { a += s_r1[w]; b += s_r2[w]; }
            s_ka[k] = a * b;      // Nb.sum(-1) * gate.sum(-1)
        }
        __syncthreads();
    }

    if (d == 0) {   // softmax over ka_weight
        float mx = s_ka[0];
#pragma unroll
        for (int k = 1; k < KK; k++) mx = fmaxf(mx, s_ka[k]);
        float z = 0.f; float pv[KK];
#pragma unroll
        for (int k = 0; k < KK; k++) { pv[k] = expf(s_ka[k] - mx); z += pv[k]; }
        const float iz = 1.f / z;
#pragma unroll
        for (int k = 0; k < KK; k++) s_p[k] = pv[k] * iz;
    }
    __syncthreads();

    float acc = 0.f;
#pragma unroll
    for (int k = 0; k < KK; k++) acc += s_p[k] * nb[k];
    eNh[(size_t)row * DD + d] = acc;
}

// ---------------- elementwise prep for lin1/lin2 ---------------------------
__global__ void prep_kernel(const float* __restrict__ eh, const float* __restrict__ eNh,
                            float* __restrict__ sumb, float* __restrict__ mulb)
{
    const int i = blockIdx.x * 256 + threadIdx.x;
    const float a = eh[i], b = eNh[i];
    sumb[i] = a + b;
    mulb[i] = a * b;
}

// ---------------- att2: [N,128] @ [128,1] (one warp / row) -----------------
__global__ void att2_kernel(const float* __restrict__ a1, const float* __restrict__ w2,
                            const float* __restrict__ b2, float* __restrict__ att)
{
    const int warp = threadIdx.x >> 5, lane = threadIdx.x & 31;
    const int row = blockIdx.x * 8 + warp;
    float s = 0.f;
    for (int c = lane; c < 128; c += 32) s += a1[(size_t)row * 128 + c] * w2[c];
#pragma unroll
    for (int off = 16; off; off >>= 1) s += __shfl_down_sync(0xffffffffu, s, off);
    if (lane == 0) att[row] = s + b2[0];
}

// ---------------- softmax-over-N stats (max, sum) --------------------------
__global__ void attstats_kernel(const float* __restrict__ att)
{
    __shared__ float sm[32], ss[32];
    const int tid = threadIdx.x;           // 1024 threads
    const int lane = tid & 31, warp = tid >> 5;
    float mx = -CUDART_INF_F;
    for (int i = tid; i < NROW; i += 1024) mx = fmaxf(mx, att[i]);
#pragma unroll
    for (int off = 16; off; off >>= 1) mx = fmaxf(mx, __shfl_xor_sync(0xffffffffu, mx, off));
    if (lane == 0) sm[warp] = mx;
    __syncthreads();
    if (tid < 32) {
        float m = sm[tid];
#pragma unroll
        for (int off = 16; off; off >>= 1) m = fmaxf(m, __shfl_xor_sync(0xffffffffu, m, off));
        if (tid == 0) sm[0] = m;
    }
    __syncthreads();
    mx = sm[0];
    float z = 0.f;
    for (int i = tid; i < NROW; i += 1024) z += expf(att[i] - mx);
#pragma unroll
    for (int off = 16; off; off >>= 1) z += __shfl_xor_sync(0xffffffffu, z, off);
    if (lane == 0) ss[warp] = z;
    __syncthreads();
    if (tid < 32) {
        float s = ss[tid];
#pragma unroll
        for (int off = 16; off; off >>= 1) s += __shfl_xor_sync(0xffffffffu, s, off);
        if (tid == 0) { g_red2[0] = mx; g_red2[1] = s; }
    }
}

// ---------------- e_g = sum_n softmax(att)_n * e[n,:] (two-stage) ----------
__global__ void eg_partial_kernel(const float* __restrict__ att, const float* __restrict__ e,
                                  float* __restrict__ part)
{
    __shared__ float s_w[128];
    const int tid = threadIdx.x, b = blockIdx.x, base = b * 128;
    const float mx = g_red2[0], iz = 1.f / g_red2[1];
    if (tid < 128) s_w[tid] = expf(att[base + tid] - mx) * iz;
    __syncthreads();
    float acc = 0.f;
    for (int r = 0; r < 128; r++) acc += s_w[r] * e[(size_t)(base + r) * DD + tid];
    part[b * DD + tid] = acc;
}

__global__ void eg_final_kernel(const float* __restrict__ part, float* __restrict__ out)
{
    const int d = threadIdx.x;
    float acc = 0.f;
    for (int b = 0; b < 64; b++) acc += part[b * DD + d];
    out[(size_t)NROW * DD + d] = acc;
}

// ---------------- launch ----------------------------------------------------
extern "C" void kernel_launch(void* const* d_in, const int* in_sizes, int n_in,
                              void* d_out, int out_size)
{
    const float* x     = (const float*)d_in[0];
    const float* Wfc1  = (const float*)d_in[1];  const float* bfc1 = (const float*)d_in[2];
    const float* Wfc2  = (const float*)d_in[3];  const float* bfc2 = (const float*)d_in[4];
    const float* Whead = (const float*)d_in[5];  const float* bhead= (const float*)d_in[6];
    const float* Wtail = (const float*)d_in[7];  const float* btail= (const float*)d_in[8];
    const float* Wlin1 = (const float*)d_in[9];  const float* blin1= (const float*)d_in[10];
    const float* Wlin2 = (const float*)d_in[11]; const float* blin2= (const float*)d_in[12];
    const float* Watt1 = (const float*)d_in[13]; const float* batt1= (const float*)d_in[14];
    const float* Watt2 = (const float*)d_in[15]; const float* batt2= (const float*)d_in[16];
    float* out = (float*)d_out;

    float *pA, *pB, *peh, *pet, *pS, *peNh, *ptw, *patt, *ppart; int* pti;
    cudaGetSymbolAddress((void**)&pA,   g_A);
    cudaGetSymbolAddress((void**)&pB,   g_B);
    cudaGetSymbolAddress((void**)&peh,  g_eh);
    cudaGetSymbolAddress((void**)&pet,  g_et);
    cudaGetSymbolAddress((void**)&pS,   g_S);
    cudaGetSymbolAddress((void**)&peNh, g_eNh);
    cudaGetSymbolAddress((void**)&ptw,  g_tw);
    cudaGetSymbolAddress((void**)&pti,  g_ti);
    cudaGetSymbolAddress((void**)&patt, g_att);
    cudaGetSymbolAddress((void**)&ppart,g_part);

    const dim3 thr(256);
    // pathology_fc
    gemm_kernel<false><<<dim3(DD/64, NROW/64), thr>>>(x,  Wfc1, bfc1, pA,  NROW, DD, DIN, 1.f, 1, 0);
    gemm_kernel<false><<<dim3(DD/64, NROW/64), thr>>>(pA, Wfc2, bfc2, pB,  NROW, DD, DD,  1.f, 1, 0);
    // head / tail embeddings
    gemm_kernel<false><<<dim3(DD/64, NROW/64), thr>>>(pB, Whead, bhead, peh, NROW, DD, DD, 1.f, 0, 0);
    gemm_kernel<false><<<dim3(DD/64, NROW/64), thr>>>(pB, Wtail, btail, pet, NROW, DD, DD, 1.f, 0, 0);
    // pairwise scores (NT): S = SCALE * e_h @ e_t^T
    gemm_kernel<true><<<dim3(NROW/64, NROW/64), thr>>>(peh, pet, nullptr, pS, NROW, NROW, DD, SCALE_F, 0, 0);
    // top-30 + gated message aggregation
    topk_kernel<<<NROW, 256>>>(pS, ptw, pti);
    message_kernel<<<NROW, 256>>>(peh, pet, ptw, pti, peNh);
    // combine branches
    prep_kernel<<<NROW * DD / 256, 256>>>(peh, peNh, pA, pB);
    gemm_kernel<false><<<dim3(DD/64, NROW/64), thr>>>(pA, Wlin1, blin1, out, NROW, DD, DD, 1.f, 1, 0);
    gemm_kernel<false><<<dim3(DD/64, NROW/64), thr>>>(pB, Wlin2, blin2, out, NROW, DD, DD, 1.f, 1, 1);
    // global attention readout
    gemm_kernel<false><<<dim3(128/64, NROW/64), thr>>>(out, Watt1, batt1, pA, NROW, 128, DD, 1.f, 2, 0);
    att2_kernel<<<NROW/8, 256>>>(pA, Watt2, batt2, patt);
    attstats_kernel<<<1, 1024>>>(patt);
    eg_partial_kernel<<<64, 256>>>(patt, out, ppart);
    eg_final_kernel<<<1, 256>>>(ppart, out);
}

// round 9
// speedup vs baseline: 1.1883x; 1.1883x over previous
#include <cuda_runtime.h>
#include <math_constants.h>

#define NROW 8192
#define DIN  1024
#define DD   256
#define KK   30
#define SCALE_F 0.0625f   // 256^-0.5

// ---------------- device scratch (no allocations allowed) ----------------
__device__ float g_A[NROW * DD];
__device__ float g_B[NROW * DD];
__device__ float g_eh[NROW * DD];
__device__ float g_et[NROW * DD];
__device__ float g_S[(size_t)NROW * NROW];     // 256 MB score matrix
__device__ float g_eNh[NROW * DD];
__device__ float g_tw[NROW * KK];
__device__ int   g_ti[NROW * KK];
__device__ float g_att[NROW];
__device__ float g_red2[2];
__device__ float g_part[64 * DD];

// ---------------- 3xTF32 tensor-core NT GEMM: S = SCALE * A @ B^T ---------
// Split-precision: x = hi + lo, acc += hi*hi + hi*lo + lo*hi  (fp32-grade).
// A,B: [8192,256] fp32 row-major. BM=BN=128, BK=16, 256 thr (8 warps 4x2).
#define SM_STRIDE 20   // 16 + 4 pad: conflict-free fragment reads

__device__ __forceinline__ unsigned f2tf32(float x) {
    unsigned r;
    asm("cvt.rna.tf32.f32 %0, %1;" : "=r"(r) : "f"(x));
    return r;
}
__device__ __forceinline__ void split_tf32(float x, unsigned &hi, unsigned &lo) {
    hi = f2tf32(x);
    lo = f2tf32(x - __uint_as_float(hi));
}
__device__ __forceinline__ void mma_tf32(float (&d)[4],
                                         unsigned a0, unsigned a1, unsigned a2, unsigned a3,
                                         unsigned b0, unsigned b1) {
    asm volatile(
        "mma.sync.aligned.m16n8k8.row.col.f32.tf32.tf32.f32 "
        "{%0,%1,%2,%3}, {%4,%5,%6,%7}, {%8,%9}, {%0,%1,%2,%3};"
        : "+f"(d[0]), "+f"(d[1]), "+f"(d[2]), "+f"(d[3])
        : "r"(a0), "r"(a1), "r"(a2), "r"(a3), "r"(b0), "r"(b1));
}

__global__ void __launch_bounds__(256)
score_gemm_kernel(const float* __restrict__ A, const float* __restrict__ B,
                  float* __restrict__ C)
{
    __shared__ unsigned Ah[128 * SM_STRIDE];
    __shared__ unsigned Al[128 * SM_STRIDE];
    __shared__ unsigned Bh[128 * SM_STRIDE];
    __shared__ unsigned Bl[128 * SM_STRIDE];

    const int tid  = threadIdx.x;
    const int lane = tid & 31, wid = tid >> 5;
    const int warp_m = wid & 3;        // 0..3 -> 32 rows each
    const int warp_n = wid >> 2;       // 0..1 -> 64 cols each
    const int g = lane >> 2, t = lane & 3;
    const size_t bm = blockIdx.y * 128, bn = blockIdx.x * 128;

    const int lr = tid >> 2;           // 0..63
    const int lk = (tid & 3) << 2;     // 0,4,8,12

    float acc[2][8][4];
#pragma unroll
    for (int i = 0; i < 2; i++)
#pragma unroll
        for (int j = 0; j < 8; j++)
#pragma unroll
            for (int c = 0; c < 4; c++) acc[i][j][c] = 0.f;

    float4 ra0, ra1, rb0, rb1;
    ra0 = *(const float4*)(A + (bm + lr)      * DD + lk);
    ra1 = *(const float4*)(A + (bm + lr + 64) * DD + lk);
    rb0 = *(const float4*)(B + (bn + lr)      * DD + lk);
    rb1 = *(const float4*)(B + (bn + lr + 64) * DD + lk);

    for (int k0 = 0; k0 < DD; k0 += 16) {
        // store current tile as hi/lo tf32 pairs
        {
            unsigned h, l; int o;
            o = lr * SM_STRIDE + lk;
            split_tf32(ra0.x, h, l); Ah[o + 0] = h; Al[o + 0] = l;
            split_tf32(ra0.y, h, l); Ah[o + 1] = h; Al[o + 1] = l;
            split_tf32(ra0.z, h, l); Ah[o + 2] = h; Al[o + 2] = l;
            split_tf32(ra0.w, h, l); Ah[o + 3] = h; Al[o + 3] = l;
            o = (lr + 64) * SM_STRIDE + lk;
            split_tf32(ra1.x, h, l); Ah[o + 0] = h; Al[o + 0] = l;
            split_tf32(ra1.y, h, l); Ah[o + 1] = h; Al[o + 1] = l;
            split_tf32(ra1.z, h, l); Ah[o + 2] = h; Al[o + 2] = l;
            split_tf32(ra1.w, h, l); Ah[o + 3] = h; Al[o + 3] = l;
            o = lr * SM_STRIDE + lk;
            split_tf32(rb0.x, h, l); Bh[o + 0] = h; Bl[o + 0] = l;
            split_tf32(rb0.y, h, l); Bh[o + 1] = h; Bl[o + 1] = l;
            split_tf32(rb0.z, h, l); Bh[o + 2] = h; Bl[o + 2] = l;
            split_tf32(rb0.w, h, l); Bh[o + 3] = h; Bl[o + 3] = l;
            o = (lr + 64) * SM_STRIDE + lk;
            split_tf32(rb1.x, h, l); Bh[o + 0] = h; Bl[o + 0] = l;
            split_tf32(rb1.y, h, l); Bh[o + 1] = h; Bl[o + 1] = l;
            split_tf32(rb1.z, h, l); Bh[o + 2] = h; Bl[o + 2] = l;
            split_tf32(rb1.w, h, l); Bh[o + 3] = h; Bl[o + 3] = l;
        }
        __syncthreads();

        // prefetch next tile while computing
        if (k0 + 16 < DD) {
            const int nk = k0 + 16 + lk;
            ra0 = *(const float4*)(A + (bm + lr)      * DD + nk);
            ra1 = *(const float4*)(A + (bm + lr + 64) * DD + nk);
            rb0 = *(const float4*)(B + (bn + lr)      * DD + nk);
            rb1 = *(const float4*)(B + (bn + lr + 64) * DD + nk);
        }

#pragma unroll
        for (int ks = 0; ks < 2; ks++) {
            const int kb = ks * 8 + t;
            unsigned afh[2][4], afl[2][4];
#pragma unroll
            for (int mt = 0; mt < 2; mt++) {
                const int row = warp_m * 32 + mt * 16 + g;
                const int r0 = row * SM_STRIDE + kb, r1 = (row + 8) * SM_STRIDE + kb;
                afh[mt][0] = Ah[r0];     afh[mt][1] = Ah[r1];
                afh[mt][2] = Ah[r0 + 4]; afh[mt][3] = Ah[r1 + 4];
                afl[mt][0] = Al[r0];     afl[mt][1] = Al[r1];
                afl[mt][2] = Al[r0 + 4]; afl[mt][3] = Al[r1 + 4];
            }
#pragma unroll
            for (int nt = 0; nt < 8; nt++) {
                const int col = (warp_n * 64 + nt * 8 + g) * SM_STRIDE + kb;
                const unsigned bh0 = Bh[col], bh1 = Bh[col + 4];
                const unsigned bl0 = Bl[col], bl1 = Bl[col + 4];
#pragma unroll
                for (int mt = 0; mt < 2; mt++) {
                    mma_tf32(acc[mt][nt], afh[mt][0], afh[mt][1], afh[mt][2], afh[mt][3], bh0, bh1);
                    mma_tf32(acc[mt][nt], afh[mt][0], afh[mt][1], afh[mt][2], afh[mt][3], bl0, bl1);
                    mma_tf32(acc[mt][nt], afl[mt][0], afl[mt][1], afl[mt][2], afl[mt][3], bh0, bh1);
                }
            }
        }
        __syncthreads();
    }

    // epilogue: scale + store
#pragma unroll
    for (int mt = 0; mt < 2; mt++) {
        const size_t r0 = bm + warp_m * 32 + mt * 16 + g;
#pragma unroll
        for (int nt = 0; nt < 8; nt++) {
            const size_t cc = bn + warp_n * 64 + nt * 8 + 2 * t;
            float2 v0 = make_float2(acc[mt][nt][0] * SCALE_F, acc[mt][nt][1] * SCALE_F);
            float2 v1 = make_float2(acc[mt][nt][2] * SCALE_F, acc[mt][nt][3] * SCALE_F);
            *(float2*)(C + r0 * NROW + cc)       = v0;
            *(float2*)(C + (r0 + 8) * NROW + cc) = v1;
        }
    }
}

// ---------------- generic tiled SGEMM: C = act(A@B + bias) (+C) ------------
__global__ void gemm_kernel(const float* __restrict__ A, const float* __restrict__ B,
                            const float* __restrict__ bias, float* __restrict__ C,
                            int M, int Nc, int Kc, int act, int accum)
{
    __shared__ float As[16][64];
    __shared__ float Bs[16][64];
    const int tid = threadIdx.x;
    const int bm = blockIdx.y * 64, bn = blockIdx.x * 64;
    const int tx = tid & 15, ty = tid >> 4;

    float acc[4][4];
#pragma unroll
    for (int i = 0; i < 4; i++)
#pragma unroll
        for (int j = 0; j < 4; j++) acc[i][j] = 0.f;

    const int arow = tid >> 2;
    const int akc  = (tid & 3) << 2;
    const int brow = tid >> 4;
    const int bcol = (tid & 15) << 2;

    for (int k0 = 0; k0 < Kc; k0 += 16) {
        float4 va = *(const float4*)(A + (size_t)(bm + arow) * Kc + k0 + akc);
        As[akc + 0][arow] = va.x; As[akc + 1][arow] = va.y;
        As[akc + 2][arow] = va.z; As[akc + 3][arow] = va.w;
        float4 vb = *(const float4*)(B + (size_t)(k0 + brow) * Nc + bn + bcol);
        *(float4*)&Bs[brow][bcol] = vb;
        __syncthreads();
#pragma unroll
        for (int k = 0; k < 16; k++) {
            float4 a4 = *(const float4*)&As[k][ty << 2];
            float4 b4 = *(const float4*)&Bs[k][tx << 2];
            float ar[4] = {a4.x, a4.y, a4.z, a4.w};
            float br[4] = {b4.x, b4.y, b4.z, b4.w};
#pragma unroll
            for (int i = 0; i < 4; i++)
#pragma unroll
                for (int j = 0; j < 4; j++) acc[i][j] += ar[i] * br[j];
        }
        __syncthreads();
    }

#pragma unroll
    for (int i = 0; i < 4; i++) {
        const int m = bm + (ty << 2) + i;
#pragma unroll
        for (int j = 0; j < 4; j++) {
            const int n = bn + (tx << 2) + j;
            float v = acc[i][j];
            if (bias) v += bias[n];
            if (act == 1) v = fmaxf(v, 0.f);
            else if (act == 2) v = v > 0.f ? v : 0.01f * v;
            const size_t o = (size_t)m * Nc + n;
            if (accum) v += C[o];
            C[o] = v;
        }
    }
}

// ---------------- top-30 per row (one block / row, owner-rescan argmax) ----
__global__ void topk_kernel(const float* __restrict__ S,
                            float* __restrict__ tw, int* __restrict__ ti)
{
    __shared__ float s_row[NROW];
    __shared__ float s_wv[8];
    __shared__ int   s_wi[8];
    __shared__ float s_bv; __shared__ int s_bi;
    const int row = blockIdx.x, tid = threadIdx.x;
    const float* Sr = S + (size_t)row * NROW;
    for (int j = tid; j < NROW; j += 256) s_row[j] = Sr[j];
    __syncthreads();

    const int base = tid << 5;
    float lv = -CUDART_INF_F; int li = 0;
#pragma unroll
    for (int j = 0; j < 32; j++) { float v = s_row[base + j]; if (v > lv) { lv = v; li = base + j; } }

    const int lane = tid & 31, warp = tid >> 5;
    for (int s = 0; s < KK; s++) {
        float v = lv; int i = li;
#pragma unroll
        for (int off = 16; off; off >>= 1) {
            float v2 = __shfl_down_sync(0xffffffffu, v, off);
            int   i2 = __shfl_down_sync(0xffffffffu, i, off);
            if (v2 > v || (v2 == v && i2 < i)) { v = v2; i = i2; }
        }
        if (lane == 0) { s_wv[warp] = v; s_wi[warp] = i; }
        __syncthreads();
        if (tid < 8) {
            v = s_wv[tid]; i = s_wi[tid];
#pragma unroll
            for (int off = 4; off; off >>= 1) {
                float v2 = __shfl_down_sync(0xffu, v, off);
                int   i2 = __shfl_down_sync(0xffu, i, off);
                if (v2 > v || (v2 == v && i2 < i)) { v = v2; i = i2; }
            }
            if (tid == 0) {
                s_bv = v; s_bi = i;
                tw[(size_t)row * KK + s] = v;
                ti[(size_t)row * KK + s] = i;
            }
        }
        __syncthreads();
        const int sel = s_bi;
        if (sel >= base && sel < base + 32) {
            s_row[sel] = -CUDART_INF_F;
            lv = -CUDART_INF_F; li = 0;
#pragma unroll
            for (int j = 0; j < 32; j++) { float vv = s_row[base + j]; if (vv > lv) { lv = vv; li = base + j; } }
        }
        __syncthreads();
    }
}

// ---------------- gated message + second softmax + aggregation -------------
__global__ void message_kernel(const float* __restrict__ eh, const float* __restrict__ et,
                               const float* __restrict__ tw, const int* __restrict__ ti,
                               float* __restrict__ eNh)
{
    __shared__ float s_p[KK];
    __shared__ float s_ka[KK];
    __shared__ float s_r1[8], s_r2[8];
    const int row = blockIdx.x, d = threadIdx.x;
    const int lane = d & 31, warp = d >> 5;

    if (d == 0) {
        float mx = tw[(size_t)row * KK];
        float pv[KK]; float z = 0.f;
#pragma unroll
        for (int k = 0; k < KK; k++) { pv[k] = expf(tw[(size_t)row * KK + k] - mx); z += pv[k]; }
        const float iz = 1.f / z;
#pragma unroll
        for (int k = 0; k < KK; k++) s_p[k] = pv[k] * iz;
    }
    __syncthreads();

    const float ehd = eh[(size_t)row * DD + d];
    float nb[KK];
#pragma unroll
    for (int k = 0; k < KK; k++) {
        const int j = ti[(size_t)row * KK + k];
        const float nbv = et[(size_t)j * DD + d];
        nb[k] = nbv;
        const float p = s_p[k];
        const float gate = tanhf((2.f - p) * ehd + p * nbv);
        float s1 = nbv, s2 = gate;
#pragma unroll
        for (int off = 16; off; off >>= 1) {
            s1 += __shfl_down_sync(0xffffffffu, s1, off);
            s2 += __shfl_down_sync(0xffffffffu, s2, off);
        }
        if (lane == 0) { s_r1[warp] = s1; s_r2[warp] = s2; }
        __syncthreads();
        if (d == 0) {
            float a = 0.f, b = 0.f;
            for (int w = 0; w < 8; w++) { a += s_r1[w]; b += s_r2[w]; }
            s_ka[k] = a * b;
        }
        __syncthreads();
    }

    if (d == 0) {
        float mx = s_ka[0];
#pragma unroll
        for (int k = 1; k < KK; k++) mx = fmaxf(mx, s_ka[k]);
        float z = 0.f; float pv[KK];
#pragma unroll
        for (int k = 0; k < KK; k++) { pv[k] = expf(s_ka[k] - mx); z += pv[k]; }
        const float iz = 1.f / z;
#pragma unroll
        for (int k = 0; k < KK; k++) s_p[k] = pv[k] * iz;
    }
    __syncthreads();

    float acc = 0.f;
#pragma unroll
    for (int k = 0; k < KK; k++) acc += s_p[k] * nb[k];
    eNh[(size_t)row * DD + d] = acc;
}

// ---------------- elementwise prep for lin1/lin2 ---------------------------
__global__ void prep_kernel(const float* __restrict__ eh, const float* __restrict__ eNh,
                            float* __restrict__ sumb, float* __restrict__ mulb)
{
    const int i = blockIdx.x * 256 + threadIdx.x;
    const float a = eh[i], b = eNh[i];
    sumb[i] = a + b;
    mulb[i] = a * b;
}

// ---------------- att2: [N,128] @ [128,1] (one warp / row) -----------------
__global__ void att2_kernel(const float* __restrict__ a1, const float* __restrict__ w2,
                            const float* __restrict__ b2, float* __restrict__ att)
{
    const int warp = threadIdx.x >> 5, lane = threadIdx.x & 31;
    const int row = blockIdx.x * 8 + warp;
    float s = 0.f;
    for (int c = lane; c < 128; c += 32) s += a1[(size_t)row * 128 + c] * w2[c];
#pragma unroll
    for (int off = 16; off; off >>= 1) s += __shfl_down_sync(0xffffffffu, s, off);
    if (lane == 0) att[row] = s + b2[0];
}

// ---------------- softmax-over-N stats (max, sum) --------------------------
__global__ void attstats_kernel(const float* __restrict__ att)
{
    __shared__ float sm[32], ss[32];
    const int tid = threadIdx.x;
    const int lane = tid & 31, warp = tid >> 5;
    float mx = -CUDART_INF_F;
    for (int i = tid; i < NROW; i += 1024) mx = fmaxf(mx, att[i]);
#pragma unroll
    for (int off = 16; off; off >>= 1) mx = fmaxf(mx, __shfl_xor_sync(0xffffffffu, mx, off));
    if (lane == 0) sm[warp] = mx;
    __syncthreads();
    if (tid < 32) {
        float m = sm[tid];
#pragma unroll
        for (int off = 16; off; off >>= 1) m = fmaxf(m, __shfl_xor_sync(0xffffffffu, m, off));
        if (tid == 0) sm[0] = m;
    }
    __syncthreads();
    mx = sm[0];
    float z = 0.f;
    for (int i = tid; i < NROW; i += 1024) z += expf(att[i] - mx);
#pragma unroll
    for (int off = 16; off; off >>= 1) z += __shfl_xor_sync(0xffffffffu, z, off);
    if (lane == 0) ss[warp] = z;
    __syncthreads();
    if (tid < 32) {
        float s = ss[tid];
#pragma unroll
        for (int off = 16; off; off >>= 1) s += __shfl_xor_sync(0xffffffffu, s, off);
        if (tid == 0) { g_red2[0] = mx; g_red2[1] = s; }
    }
}

// ---------------- e_g = sum_n softmax(att)_n * e[n,:] ----------------------
__global__ void eg_partial_kernel(const float* __restrict__ att, const float* __restrict__ e,
                                  float* __restrict__ part)
{
    __shared__ float s_w[128];
    const int tid = threadIdx.x, b = blockIdx.x, base = b * 128;
    const float mx = g_red2[0], iz = 1.f / g_red2[1];
    if (tid < 128) s_w[tid] = expf(att[base + tid] - mx) * iz;
    __syncthreads();
    float acc = 0.f;
    for (int r = 0; r < 128; r++) acc += s_w[r] * e[(size_t)(base + r) * DD + tid];
    part[b * DD + tid] = acc;
}

__global__ void eg_final_kernel(const float* __restrict__ part, float* __restrict__ out)
{
    const int d = threadIdx.x;
    float acc = 0.f;
    for (int b = 0; b < 64; b++) acc += part[b * DD + d];
    out[(size_t)NROW * DD + d] = acc;
}

// ---------------- launch ----------------------------------------------------
extern "C" void kernel_launch(void* const* d_in, const int* in_sizes, int n_in,
                              void* d_out, int out_size)
{
    const float* x     = (const float*)d_in[0];
    const float* Wfc1  = (const float*)d_in[1];  const float* bfc1 = (const float*)d_in[2];
    const float* Wfc2  = (const float*)d_in[3];  const float* bfc2 = (const float*)d_in[4];
    const float* Whead = (const float*)d_in[5];  const float* bhead= (const float*)d_in[6];
    const float* Wtail = (const float*)d_in[7];  const float* btail= (const float*)d_in[8];
    const float* Wlin1 = (const float*)d_in[9];  const float* blin1= (const float*)d_in[10];
    const float* Wlin2 = (const float*)d_in[11]; const float* blin2= (const float*)d_in[12];
    const float* Watt1 = (const float*)d_in[13]; const float* batt1= (const float*)d_in[14];
    const float* Watt2 = (const float*)d_in[15]; const float* batt2= (const float*)d_in[16];
    float* out = (float*)d_out;

    float *pA, *pB, *peh, *pet, *pS, *peNh, *ptw, *patt, *ppart; int* pti;
    cudaGetSymbolAddress((void**)&pA,   g_A);
    cudaGetSymbolAddress((void**)&pB,   g_B);
    cudaGetSymbolAddress((void**)&peh,  g_eh);
    cudaGetSymbolAddress((void**)&pet,  g_et);
    cudaGetSymbolAddress((void**)&pS,   g_S);
    cudaGetSymbolAddress((void**)&peNh, g_eNh);
    cudaGetSymbolAddress((void**)&ptw,  g_tw);
    cudaGetSymbolAddress((void**)&pti,  g_ti);
    cudaGetSymbolAddress((void**)&patt, g_att);
    cudaGetSymbolAddress((void**)&ppart,g_part);

    const dim3 thr(256);
    // pathology_fc
    gemm_kernel<<<dim3(DD/64, NROW/64), thr>>>(x,  Wfc1, bfc1, pA,  NROW, DD, DIN, 1, 0);
    gemm_kernel<<<dim3(DD/64, NROW/64), thr>>>(pA, Wfc2, bfc2, pB,  NROW, DD, DD,  1, 0);
    // head / tail embeddings
    gemm_kernel<<<dim3(DD/64, NROW/64), thr>>>(pB, Whead, bhead, peh, NROW, DD, DD, 0, 0);
    gemm_kernel<<<dim3(DD/64, NROW/64), thr>>>(pB, Wtail, btail, pet, NROW, DD, DD, 0, 0);
    // pairwise scores: S = SCALE * e_h @ e_t^T   (3xTF32 tensor cores)
    score_gemm_kernel<<<dim3(NROW/128, NROW/128), thr>>>(peh, pet, pS);
    // top-30 + gated message aggregation
    topk_kernel<<<NROW, 256>>>(pS, ptw, pti);
    message_kernel<<<NROW, 256>>>(peh, pet, ptw, pti, peNh);
    // combine branches
    prep_kernel<<<NROW * DD / 256, 256>>>(peh, peNh, pA, pB);
    gemm_kernel<<<dim3(DD/64, NROW/64), thr>>>(pA, Wlin1, blin1, out, NROW, DD, DD, 1, 0);
    gemm_kernel<<<dim3(DD/64, NROW/64), thr>>>(pB, Wlin2, blin2, out, NROW, DD, DD, 1, 1);
    // global attention readout
    gemm_kernel<<<dim3(128/64, NROW/64), thr>>>(out, Watt1, batt1, pA, NROW, 128, DD, 2, 0);
    att2_kernel<<<NROW/8, 256>>>(pA, Watt2, batt2, patt);
    attstats_kernel<<<1, 1024>>>(patt);
    eg_partial_kernel<<<64, 256>>>(patt, out, ppart);
    eg_final_kernel<<<1, 256>>>(ppart, out);
}

// round 15
// speedup vs baseline: 1.2329x; 1.0375x over previous
#include <cuda_runtime.h>
#include <math_constants.h>
#include <cstdint>

#define NROW 8192
#define DIN  1024
#define DD   256
#define KK   30
#define SCALE_F 0.0625f   // 256^-0.5

// ---------------- device scratch (no allocations allowed) ----------------
__device__ float g_A[NROW * DD];
__device__ float g_B[NROW * DD];
__device__ float g_eh[NROW * DD];
__device__ float g_et[NROW * DD];
__device__ float g_S[(size_t)NROW * NROW];     // 256 MB score matrix
__device__ float g_eNh[NROW * DD];
__device__ float g_tw[NROW * KK];
__device__ int   g_ti[NROW * KK];
__device__ float g_att[NROW];
__device__ float g_red2[2];
__device__ float g_part[64 * DD];

// ---------------- 3xTF32 helpers ------------------------------------------
#define SM_STRIDE 20   // 16 + 4 pad: conflict-free fragment reads

__device__ __forceinline__ unsigned f2tf32(float x) {
    unsigned r;
    asm("cvt.rna.tf32.f32 %0, %1;" : "=r"(r) : "f"(x));
    return r;
}
__device__ __forceinline__ void split_tf32(float x, unsigned &hi, unsigned &lo) {
    hi = f2tf32(x);
    lo = f2tf32(x - __uint_as_float(hi));
}
__device__ __forceinline__ void mma_tf32(float (&d)[4],
                                         unsigned a0, unsigned a1, unsigned a2, unsigned a3,
                                         unsigned b0, unsigned b1) {
    asm volatile(
        "mma.sync.aligned.m16n8k8.row.col.f32.tf32.tf32.f32 "
        "{%0,%1,%2,%3}, {%4,%5,%6,%7}, {%8,%9}, {%0,%1,%2,%3};"
        : "+f"(d[0]), "+f"(d[1]), "+f"(d[2]), "+f"(d[3])
        : "r"(a0), "r"(a1), "r"(a2), "r"(a3), "r"(b0), "r"(b1));
}

// ---------------- 3xTF32 NT GEMM: S = SCALE * A @ B^T (UNCHANGED, passing) -
__global__ void __launch_bounds__(256)
score_gemm_kernel(const float* __restrict__ A, const float* __restrict__ B,
                  float* __restrict__ C)
{
    __shared__ unsigned Ah[128 * SM_STRIDE];
    __shared__ unsigned Al[128 * SM_STRIDE];
    __shared__ unsigned Bh[128 * SM_STRIDE];
    __shared__ unsigned Bl[128 * SM_STRIDE];

    const int tid  = threadIdx.x;
    const int lane = tid & 31, wid = tid >> 5;
    const int warp_m = wid & 3;
    const int warp_n = wid >> 2;
    const int g = lane >> 2, t = lane & 3;
    const size_t bm = blockIdx.y * 128, bn = blockIdx.x * 128;

    const int lr = tid >> 2;
    const int lk = (tid & 3) << 2;

    float acc[2][8][4];
#pragma unroll
    for (int i = 0; i < 2; i++)
#pragma unroll
        for (int j = 0; j < 8; j++)
#pragma unroll
            for (int c = 0; c < 4; c++) acc[i][j][c] = 0.f;

    float4 ra0, ra1, rb0, rb1;
    ra0 = *(const float4*)(A + (bm + lr)      * DD + lk);
    ra1 = *(const float4*)(A + (bm + lr + 64) * DD + lk);
    rb0 = *(const float4*)(B + (bn + lr)      * DD + lk);
    rb1 = *(const float4*)(B + (bn + lr + 64) * DD + lk);

    for (int k0 = 0; k0 < DD; k0 += 16) {
        {
            unsigned h, l; int o;
            o = lr * SM_STRIDE + lk;
            split_tf32(ra0.x, h, l); Ah[o + 0] = h; Al[o + 0] = l;
            split_tf32(ra0.y, h, l); Ah[o + 1] = h; Al[o + 1] = l;
            split_tf32(ra0.z, h, l); Ah[o + 2] = h; Al[o + 2] = l;
            split_tf32(ra0.w, h, l); Ah[o + 3] = h; Al[o + 3] = l;
            o = (lr + 64) * SM_STRIDE + lk;
            split_tf32(ra1.x, h, l); Ah[o + 0] = h; Al[o + 0] = l;
            split_tf32(ra1.y, h, l); Ah[o + 1] = h; Al[o + 1] = l;
            split_tf32(ra1.z, h, l); Ah[o + 2] = h; Al[o + 2] = l;
            split_tf32(ra1.w, h, l); Ah[o + 3] = h; Al[o + 3] = l;
            o = lr * SM_STRIDE + lk;
            split_tf32(rb0.x, h, l); Bh[o + 0] = h; Bl[o + 0] = l;
            split_tf32(rb0.y, h, l); Bh[o + 1] = h; Bl[o + 1] = l;
            split_tf32(rb0.z, h, l); Bh[o + 2] = h; Bl[o + 2] = l;
            split_tf32(rb0.w, h, l); Bh[o + 3] = h; Bl[o + 3] = l;
            o = (lr + 64) * SM_STRIDE + lk;
            split_tf32(rb1.x, h, l); Bh[o + 0] = h; Bl[o + 0] = l;
            split_tf32(rb1.y, h, l); Bh[o + 1] = h; Bl[o + 1] = l;
            split_tf32(rb1.z, h, l); Bh[o + 2] = h; Bl[o + 2] = l;
            split_tf32(rb1.w, h, l); Bh[o + 3] = h; Bl[o + 3] = l;
        }
        __syncthreads();

        if (k0 + 16 < DD) {
            const int nk = k0 + 16 + lk;
            ra0 = *(const float4*)(A + (bm + lr)      * DD + nk);
            ra1 = *(const float4*)(A + (bm + lr + 64) * DD + nk);
            rb0 = *(const float4*)(B + (bn + lr)      * DD + nk);
            rb1 = *(const float4*)(B + (bn + lr + 64) * DD + nk);
        }

#pragma unroll
        for (int ks = 0; ks < 2; ks++) {
            const int kb = ks * 8 + t;
            unsigned afh[2][4], afl[2][4];
#pragma unroll
            for (int mt = 0; mt < 2; mt++) {
                const int row = warp_m * 32 + mt * 16 + g;
                const int r0 = row * SM_STRIDE + kb, r1 = (row + 8) * SM_STRIDE + kb;
                afh[mt][0] = Ah[r0];     afh[mt][1] = Ah[r1];
                afh[mt][2] = Ah[r0 + 4]; afh[mt][3] = Ah[r1 + 4];
                afl[mt][0] = Al[r0];     afl[mt][1] = Al[r1];
                afl[mt][2] = Al[r0 + 4]; afl[mt][3] = Al[r1 + 4];
            }
#pragma unroll
            for (int nt = 0; nt < 8; nt++) {
                const int col = (warp_n * 64 + nt * 8 + g) * SM_STRIDE + kb;
                const unsigned bh0 = Bh[col], bh1 = Bh[col + 4];
                const unsigned bl0 = Bl[col], bl1 = Bl[col + 4];
#pragma unroll
                for (int mt = 0; mt < 2; mt++) {
                    mma_tf32(acc[mt][nt], afh[mt][0], afh[mt][1], afh[mt][2], afh[mt][3], bh0, bh1);
                    mma_tf32(acc[mt][nt], afh[mt][0], afh[mt][1], afh[mt][2], afh[mt][3], bl0, bl1);
                    mma_tf32(acc[mt][nt], afl[mt][0], afl[mt][1], afl[mt][2], afl[mt][3], bh0, bh1);
                }
            }
        }
        __syncthreads();
    }

#pragma unroll
    for (int mt = 0; mt < 2; mt++) {
        const size_t r0 = bm + warp_m * 32 + mt * 16 + g;
#pragma unroll
        for (int nt = 0; nt < 8; nt++) {
            const size_t cc = bn + warp_n * 64 + nt * 8 + 2 * t;
            float2 v0 = make_float2(acc[mt][nt][0] * SCALE_F, acc[mt][nt][1] * SCALE_F);
            float2 v1 = make_float2(acc[mt][nt][2] * SCALE_F, acc[mt][nt][3] * SCALE_F);
            *(float2*)(C + r0 * NROW + cc)       = v0;
            *(float2*)(C + (r0 + 8) * NROW + cc) = v1;
        }
    }
}

// ---------------- 3xTF32 TN GEMM: C = act(A[M,K]@B[K,N] + bias) (+C) -------
// BM=128, BN=128, BK=16, 256 threads, same fragment machinery as score.
__global__ void __launch_bounds__(256)
tc_gemm_tn(const float* __restrict__ A, const float* __restrict__ B,
           const float* __restrict__ bias, float* __restrict__ C,
           int M, int Nc, int Kc, int act, int accum)
{
    __shared__ unsigned Ah[128 * SM_STRIDE];
    __shared__ unsigned Al[128 * SM_STRIDE];
    __shared__ unsigned Bh[128 * SM_STRIDE];
    __shared__ unsigned Bl[128 * SM_STRIDE];

    const int tid  = threadIdx.x;
    const int lane = tid & 31, wid = tid >> 5;
    const int warp_m = wid & 3;
    const int warp_n = wid >> 2;
    const int g = lane >> 2, t = lane & 3;
    const size_t bm = blockIdx.y * 128, bn = blockIdx.x * 128;

    // A: 2 rows x float4 per thread
    const int lr = tid >> 2;
    const int lk = (tid & 3) << 2;
    // B: row k0+kr, 8 cols starting at ng (transposed store)
    const int kr = tid & 15;
    const int ng = (tid >> 4) << 3;

    float acc[2][8][4];
#pragma unroll
    for (int i = 0; i < 2; i++)
#pragma unroll
        for (int j = 0; j < 8; j++)
#pragma unroll
            for (int c = 0; c < 4; c++) acc[i][j][c] = 0.f;

    float4 ra0, ra1, rb0, rb1;
    ra0 = *(const float4*)(A + (bm + lr)      * Kc + lk);
    ra1 = *(const float4*)(A + (bm + lr + 64) * Kc + lk);
    rb0 = *(const float4*)(B + (size_t)kr * Nc + bn + ng);
    rb1 = *(const float4*)(B + (size_t)kr * Nc + bn + ng + 4);

    for (int k0 = 0; k0 < Kc; k0 += 16) {
        {
            unsigned h, l; int o;
            o = lr * SM_STRIDE + lk;
            split_tf32(ra0.x, h, l); Ah[o + 0] = h; Al[o + 0] = l;
            split_tf32(ra0.y, h, l); Ah[o + 1] = h; Al[o + 1] = l;
            split_tf32(ra0.z, h, l); Ah[o + 2] = h; Al[o + 2] = l;
            split_tf32(ra0.w, h, l); Ah[o + 3] = h; Al[o + 3] = l;
            o = (lr + 64) * SM_STRIDE + lk;
            split_tf32(ra1.x, h, l); Ah[o + 0] = h; Al[o + 0] = l;
            split_tf32(ra1.y, h, l); Ah[o + 1] = h; Al[o + 1] = l;
            split_tf32(ra1.z, h, l); Ah[o + 2] = h; Al[o + 2] = l;
            split_tf32(ra1.w, h, l); Ah[o + 3] = h; Al[o + 3] = l;
            // transposed B store: Bs[n][k] = B[k][n]
            split_tf32(rb0.x, h, l); Bh[(ng + 0) * SM_STRIDE + kr] = h; Bl[(ng + 0) * SM_STRIDE + kr] = l;
            split_tf32(rb0.y, h, l); Bh[(ng + 1) * SM_STRIDE + kr] = h; Bl[(ng + 1) * SM_STRIDE + kr] = l;
            split_tf32(rb0.z, h, l); Bh[(ng + 2) * SM_STRIDE + kr] = h; Bl[(ng + 2) * SM_STRIDE + kr] = l;
            split_tf32(rb0.w, h, l); Bh[(ng + 3) * SM_STRIDE + kr] = h; Bl[(ng + 3) * SM_STRIDE + kr] = l;
            split_tf32(rb1.x, h, l); Bh[(ng + 4) * SM_STRIDE + kr] = h; Bl[(ng + 4) * SM_STRIDE + kr] = l;
            split_tf32(rb1.y, h, l); Bh[(ng + 5) * SM_STRIDE + kr] = h; Bl[(ng + 5) * SM_STRIDE + kr] = l;
            split_tf32(rb1.z, h, l); Bh[(ng + 6) * SM_STRIDE + kr] = h; Bl[(ng + 6) * SM_STRIDE + kr] = l;
            split_tf32(rb1.w, h, l); Bh[(ng + 7) * SM_STRIDE + kr] = h; Bl[(ng + 7) * SM_STRIDE + kr] = l;
        }
        __syncthreads();

        if (k0 + 16 < Kc) {
            const int nk = k0 + 16;
            ra0 = *(const float4*)(A + (bm + lr)      * Kc + nk + lk);
            ra1 = *(const float4*)(A + (bm + lr + 64) * Kc + nk + lk);
            rb0 = *(const float4*)(B + (size_t)(nk + kr) * Nc + bn + ng);
            rb1 = *(const float4*)(B + (size_t)(nk + kr) * Nc + bn + ng + 4);
        }

#pragma unroll
        for (int ks = 0; ks < 2; ks++) {
            const int kb = ks * 8 + t;
            unsigned afh[2][4], afl[2][4];
#pragma unroll
            for (int mt = 0; mt < 2; mt++) {
                const int row = warp_m * 32 + mt * 16 + g;
                const int r0 = row * SM_STRIDE + kb, r1 = (row + 8) * SM_STRIDE + kb;
                afh[mt][0] = Ah[r0];     afh[mt][1] = Ah[r1];
                afh[mt][2] = Ah[r0 + 4]; afh[mt][3] = Ah[r1 + 4];
                afl[mt][0] = Al[r0];     afl[mt][1] = Al[r1];
                afl[mt][2] = Al[r0 + 4]; afl[mt][3] = Al[r1 + 4];
            }
#pragma unroll
            for (int nt = 0; nt < 8; nt++) {
                const int col = (warp_n * 64 + nt * 8 + g) * SM_STRIDE + kb;
                const unsigned bh0 = Bh[col], bh1 = Bh[col + 4];
                const unsigned bl0 = Bl[col], bl1 = Bl[col + 4];
#pragma unroll
                for (int mt = 0; mt < 2; mt++) {
                    mma_tf32(acc[mt][nt], afh[mt][0], afh[mt][1], afh[mt][2], afh[mt][3], bh0, bh1);
                    mma_tf32(acc[mt][nt], afh[mt][0], afh[mt][1], afh[mt][2], afh[mt][3], bl0, bl1);
                    mma_tf32(acc[mt][nt], afl[mt][0], afl[mt][1], afl[mt][2], afl[mt][3], bh0, bh1);
                }
            }
        }
        __syncthreads();
    }

#pragma unroll
    for (int mt = 0; mt < 2; mt++) {
        const size_t r0 = bm + warp_m * 32 + mt * 16 + g;
#pragma unroll
        for (int nt = 0; nt < 8; nt++) {
            const size_t cc = bn + warp_n * 64 + nt * 8 + 2 * t;
            const float b0 = bias[cc], b1 = bias[cc + 1];
            float v[4];
            v[0] = acc[mt][nt][0] + b0; v[1] = acc[mt][nt][1] + b1;
            v[2] = acc[mt][nt][2] + b0; v[3] = acc[mt][nt][3] + b1;
            if (act == 1) {
#pragma unroll
                for (int c = 0; c < 4; c++) v[c] = fmaxf(v[c], 0.f);
            } else if (act == 2) {
#pragma unroll
                for (int c = 0; c < 4; c++) v[c] = v[c] > 0.f ? v[c] : 0.01f * v[c];
            }
            const size_t o0 = r0 * Nc + cc, o1 = (r0 + 8) * Nc + cc;
            if (accum) { v[0] += C[o0]; v[1] += C[o0 + 1]; v[2] += C[o1]; v[3] += C[o1 + 1]; }
            *(float2*)(C + o0) = make_float2(v[0], v[1]);
            *(float2*)(C + o1) = make_float2(v[2], v[3]);
        }
    }
}

// ---------------- top-30 per row (one block / row, owner-rescan argmax) ----
__global__ void topk_kernel(const float* __restrict__ S,
                            float* __restrict__ tw, int* __restrict__ ti)
{
    __shared__ float s_row[NROW];
    __shared__ float s_wv[8];
    __shared__ int   s_wi[8];
    __shared__ float s_bv; __shared__ int s_bi;
    const int row = blockIdx.x, tid = threadIdx.x;
    const float* Sr = S + (size_t)row * NROW;
    for (int j = tid; j < NROW; j += 256) s_row[j] = Sr[j];
    __syncthreads();

    const int base = tid << 5;
    float lv = -CUDART_INF_F; int li = 0;
#pragma unroll
    for (int j = 0; j < 32; j++) { float v = s_row[base + j]; if (v > lv) { lv = v; li = base + j; } }

    const int lane = tid & 31, warp = tid >> 5;
    for (int s = 0; s < KK; s++) {
        float v = lv; int i = li;
#pragma unroll
        for (int off = 16; off; off >>= 1) {
            float v2 = __shfl_down_sync(0xffffffffu, v, off);
            int   i2 = __shfl_down_sync(0xffffffffu, i, off);
            if (v2 > v || (v2 == v && i2 < i)) { v = v2; i = i2; }
        }
        if (lane == 0) { s_wv[warp] = v; s_wi[warp] = i; }
        __syncthreads();
        if (tid < 8) {
            v = s_wv[tid]; i = s_wi[tid];
#pragma unroll
            for (int off = 4; off; off >>= 1) {
                float v2 = __shfl_down_sync(0xffu, v, off);
                int   i2 = __shfl_down_sync(0xffu, i, off);
                if (v2 > v || (v2 == v && i2 < i)) { v = v2; i = i2; }
            }
            if (tid == 0) {
                s_bv = v; s_bi = i;
                tw[(size_t)row * KK + s] = v;
                ti[(size_t)row * KK + s] = i;
            }
        }
        __syncthreads();
        const int sel = s_bi;
        if (sel >= base && sel < base + 32) {
            s_row[sel] = -CUDART_INF_F;
            lv = -CUDART_INF_F; li = 0;
#pragma unroll
            for (int j = 0; j < 32; j++) { float vv = s_row[base + j]; if (vv > lv) { lv = vv; li = base + j; } }
        }
        __syncthreads();
    }
}

// ---------------- gated message + second softmax + aggregation -------------
// Restructured: per-k warp partials to smem, 2 barriers total (was 60).
__global__ void message_kernel(const float* __restrict__ eh, const float* __restrict__ et,
                               const float* __restrict__ tw, const int* __restrict__ ti,
                               float* __restrict__ eNh)
{
    __shared__ float s_p[KK];
    __shared__ float s_ka[KK];
    __shared__ float s_r1[KK * 8], s_r2[KK * 8];
    const int row = blockIdx.x, d = threadIdx.x;
    const int lane = d & 31, warp = d >> 5;

    if (d == 0) {   // softmax over top-k logits (sorted desc, [0] is max)
        float mx = tw[(size_t)row * KK];
        float pv[KK]; float z = 0.f;
#pragma unroll
        for (int k = 0; k < KK; k++) { pv[k] = expf(tw[(size_t)row * KK + k] - mx); z += pv[k]; }
        const float iz = 1.f / z;
#pragma unroll
        for (int k = 0; k < KK; k++) s_p[k] = pv[k] * iz;
    }
    __syncthreads();

    const float ehd = eh[(size_t)row * DD + d];
    float nb[KK];
#pragma unroll
    for (int k = 0; k < KK; k++) {
        const int j = ti[(size_t)row * KK + k];
        const float nbv = et[(size_t)j * DD + d];
        nb[k] = nbv;
        const float p = s_p[k];
        // gate = tanh(e_h + p*Nb + (1-p)*e_h) = tanh((2-p)*e_h + p*Nb)
        const float gate = tanhf((2.f - p) * ehd + p * nbv);
        float s1 = nbv, s2 = gate;
#pragma unroll
        for (int off = 16; off; off >>= 1) {
            s1 += __shfl_down_sync(0xffffffffu, s1, off);
            s2 += __shfl_down_sync(0xffffffffu, s2, off);
        }
        if (lane == 0) { s_r1[k * 8 + warp] = s1; s_r2[k * 8 + warp] = s2; }
    }
    __syncthreads();

    if (d < KK) {
        float a = 0.f, b = 0.f;
#pragma unroll
        for (int w = 0; w < 8; w++) { a += s_r1[d * 8 + w]; b += s_r2[d * 8 + w]; }
        s_ka[d] = a * b;      // Nb.sum(-1) * gate.sum(-1)
    }
    __syncthreads();

    // per-thread redundant softmax over 30 ka weights (registers only)
    float ka[KK];
#pragma unroll
    for (int k = 0; k < KK; k++) ka[k] = s_ka[k];
    float mx = ka[0];
#pragma unroll
    for (int k = 1; k < KK; k++) mx = fmaxf(mx, ka[k]);
    float z = 0.f;
#pragma unroll
    for (int k = 0; k < KK; k++) { ka[k] = expf(ka[k] - mx); z += ka[k]; }
    const float iz = 1.f / z;

    float acc = 0.f;
#pragma unroll
    for (int k = 0; k < KK; k++) acc += ka[k] * iz * nb[k];
    eNh[(size_t)row * DD + d] = acc;
}

// ---------------- elementwise prep for lin1/lin2 ---------------------------
__global__ void prep_kernel(const float* __restrict__ eh, const float* __restrict__ eNh,
                            float* __restrict__ sumb, float* __restrict__ mulb)
{
    const int i = blockIdx.x * 256 + threadIdx.x;
    const float a = eh[i], b = eNh[i];
    sumb[i] = a + b;
    mulb[i] = a * b;
}

// ---------------- att2: [N,128] @ [128,1] (one warp / row) -----------------
__global__ void att2_kernel(const float* __restrict__ a1, const float* __restrict__ w2,
                            const float* __restrict__ b2, float* __restrict__ att)
{
    const int warp = threadIdx.x >> 5, lane = threadIdx.x & 31;
    const int row = blockIdx.x * 8 + warp;
    float s = 0.f;
    for (int c = lane; c < 128; c += 32) s += a1[(size_t)row * 128 + c] * w2[c];
#pragma unroll
    for (int off = 16; off; off >>= 1) s += __shfl_down_sync(0xffffffffu, s, off);
    if (lane == 0) att[row] = s + b2[0];
}

// ---------------- softmax-over-N stats (max, sum) --------------------------
__global__ void attstats_kernel(const float* __restrict__ att)
{
    __shared__ float sm[32], ss[32];
    const int tid = threadIdx.x;
    const int lane = tid & 31, warp = tid >> 5;
    float mx = -CUDART_INF_F;
    for (int i = tid; i < NROW; i += 1024) mx = fmaxf(mx, att[i]);
#pragma unroll
    for (int off = 16; off; off >>= 1) mx = fmaxf(mx, __shfl_xor_sync(0xffffffffu, mx, off));
    if (lane == 0) sm[warp] = mx;
    __syncthreads();
    if (tid < 32) {
        float m = sm[tid];
#pragma unroll
        for (int off = 16; off; off >>= 1) m = fmaxf(m, __shfl_xor_sync(0xffffffffu, m, off));
        if (tid == 0) sm[0] = m;
    }
    __syncthreads();
    mx = sm[0];
    float z = 0.f;
    for (int i = tid; i < NROW; i += 1024) z += expf(att[i] - mx);
#pragma unroll
    for (int off = 16; off; off >>= 1) z += __shfl_xor_sync(0xffffffffu, z, off);
    if (lane == 0) ss[warp] = z;
    __syncthreads();
    if (tid < 32) {
        float s = ss[tid];
#pragma unroll
        for (int off = 16; off; off >>= 1) s += __shfl_xor_sync(0xffffffffu, s, off);
        if (tid == 0) { g_red2[0] = mx; g_red2[1] = s; }
    }
}

// ---------------- e_g = sum_n softmax(att)_n * e[n,:] ----------------------
__global__ void eg_partial_kernel(const float* __restrict__ att, const float* __restrict__ e,
                                  float* __restrict__ part)
{
    __shared__ float s_w[128];
    const int tid = threadIdx.x, b = blockIdx.x, base = b * 128;
    const float mx = g_red2[0], iz = 1.f / g_red2[1];
    if (tid < 128) s_w[tid] = expf(att[base + tid] - mx) * iz;
    __syncthreads();
    float acc = 0.f;
    for (int r = 0; r < 128; r++) acc += s_w[r] * e[(size_t)(base + r) * DD + tid];
    part[b * DD + tid] = acc;
}

__global__ void eg_final_kernel(const float* __restrict__ part, float* __restrict__ out)
{
    const int d = threadIdx.x;
    float acc = 0.f;
    for (int b = 0; b < 64; b++) acc += part[b * DD + d];
    out[(size_t)NROW * DD + d] = acc;
}

// ---------------- launch ----------------------------------------------------
extern "C" void kernel_launch(void* const* d_in, const int* in_sizes, int n_in,
                              void* d_out, int out_size)
{
    const float* x     = (const float*)d_in[0];
    const float* Wfc1  = (const float*)d_in[1];  const float* bfc1 = (const float*)d_in[2];
    const float* Wfc2  = (const float*)d_in[3];  const float* bfc2 = (const float*)d_in[4];
    const float* Whead = (const float*)d_in[5];  const float* bhead= (const float*)d_in[6];
    const float* Wtail = (const float*)d_in[7];  const float* btail= (const float*)d_in[8];
    const float* Wlin1 = (const float*)d_in[9];  const float* blin1= (const float*)d_in[10];
    const float* Wlin2 = (const float*)d_in[11]; const float* blin2= (const float*)d_in[12];
    const float* Watt1 = (const float*)d_in[13]; const float* batt1= (const float*)d_in[14];
    const float* Watt2 = (const float*)d_in[15]; const float* batt2= (const float*)d_in[16];
    float* out = (float*)d_out;

    float *pA, *pB, *peh, *pet, *pS, *peNh, *ptw, *patt, *ppart; int* pti;
    cudaGetSymbolAddress((void**)&pA,   g_A);
    cudaGetSymbolAddress((void**)&pB,   g_B);
    cudaGetSymbolAddress((void**)&peh,  g_eh);
    cudaGetSymbolAddress((void**)&pet,  g_et);
    cudaGetSymbolAddress((void**)&pS,   g_S);
    cudaGetSymbolAddress((void**)&peNh, g_eNh);
    cudaGetSymbolAddress((void**)&ptw,  g_tw);
    cudaGetSymbolAddress((void**)&pti,  g_ti);
    cudaGetSymbolAddress((void**)&patt, g_att);
    cudaGetSymbolAddress((void**)&ppart,g_part);

    const dim3 thr(256);
    // pathology_fc  (tensor cores, 3xTF32)
    tc_gemm_tn<<<dim3(DD/128, NROW/128), thr>>>(x,  Wfc1, bfc1, pA,  NROW, DD, DIN, 1, 0);
    tc_gemm_tn<<<dim3(DD/128, NROW/128), thr>>>(pA, Wfc2, bfc2, pB,  NROW, DD, DD,  1, 0);
    // head / tail embeddings
    tc_gemm_tn<<<dim3(DD/128, NROW/128), thr>>>(pB, Whead, bhead, peh, NROW, DD, DD, 0, 0);
    tc_gemm_tn<<<dim3(DD/128, NROW/128), thr>>>(pB, Wtail, btail, pet, NROW, DD, DD, 0, 0);
    // pairwise scores: S = SCALE * e_h @ e_t^T   (3xTF32 tensor cores)
    score_gemm_kernel<<<dim3(NROW/128, NROW/128), thr>>>(peh, pet, pS);
    // top-30 + gated message aggregation
    topk_kernel<<<NROW, 256>>>(pS, ptw, pti);
    message_kernel<<<NROW, 256>>>(peh, pet, ptw, pti, peNh);
    // combine branches
    prep_kernel<<<NROW * DD / 256, 256>>>(peh, peNh, pA, pB);
    tc_gemm_tn<<<dim3(DD/128, NROW/128), thr>>>(pA, Wlin1, blin1, out, NROW, DD, DD, 1, 0);
    tc_gemm_tn<<<dim3(DD/128, NROW/128), thr>>>(pB, Wlin2, blin2, out, NROW, DD, DD, 1, 1);
    // global attention readout
    tc_gemm_tn<<<dim3(128/128, NROW/128), thr>>>(out, Watt1, batt1, pA, NROW, 128, DD, 2, 0);
    att2_kernel<<<NROW/8, 256>>>(pA, Watt2, batt2, patt);
    attstats_kernel<<<1, 1024>>>(patt);
    eg_partial_kernel<<<64, 256>>>(patt, out, ppart);
    eg_final_kernel<<<1, 256>>>(ppart, out);
}